// round 8
// baseline (speedup 1.0000x reference)
#include <cuda_runtime.h>
#include <cuda_bf16.h>
#include <cstdint>
#include <math.h>

#define Tn 8192
#define Sn 1024
#define Bn 8
#define Hn 8
#define Un 64
#define Dn 512
#define Fn 2048

typedef __nv_bfloat16 bf16;
typedef __nv_bfloat162 bf162;

// ---------------- scratch ----------------------------------------------------
__device__ bf16 g_xh[(size_t)Tn * Dn];
__device__ bf16 g_xl[(size_t)Tn * Dn];
__device__ bf16 g_qwTh[(size_t)Hn * Un * Dn];
__device__ bf16 g_qwTl[(size_t)Hn * Un * Dn];
__device__ bf16 g_kwTh[(size_t)Hn * Un * Dn];
__device__ bf16 g_kwTl[(size_t)Hn * Un * Dn];
__device__ bf16 g_vwTh[(size_t)Hn * Dn * Dn];
__device__ bf16 g_vwTl[(size_t)Hn * Dn * Dn];
__device__ bf16 g_lwTh[(size_t)Dn * Hn * Dn];
__device__ bf16 g_lwTl[(size_t)Dn * Hn * Dn];
__device__ bf16 g_w1Th[(size_t)Fn * Dn];
__device__ bf16 g_w1Tl[(size_t)Fn * Dn];
__device__ bf16 g_w2Th[(size_t)Dn * Fn];
__device__ bf16 g_w2Tl[(size_t)Dn * Fn];
__device__ bf16 g_Qh[(size_t)Hn * Tn * Un];
__device__ bf16 g_Ql[(size_t)Hn * Tn * Un];
__device__ bf16 g_Kh[(size_t)Hn * Tn * Un];
__device__ bf16 g_Kl[(size_t)Hn * Tn * Un];
__device__ bf16 g_VTh[(size_t)Hn * Dn * Tn];
__device__ bf16 g_VTl[(size_t)Hn * Dn * Tn];
__device__ float g_S[(size_t)Hn * Bn * Sn * Sn];
__device__ bf16 g_Ph[(size_t)Hn * Bn * Sn * Sn];
__device__ bf16 g_Pl[(size_t)Hn * Bn * Sn * Sn];
__device__ bf16 g_Ach[(size_t)Tn * Hn * Dn];
__device__ bf16 g_Acl[(size_t)Tn * Hn * Dn];
__device__ float g_mha[(size_t)Tn * Dn];
__device__ float g_hb[(size_t)Tn * Dn];
__device__ bf16 g_hbh[(size_t)Tn * Dn];
__device__ bf16 g_hbl[(size_t)Tn * Dn];
__device__ bf16 g_f1h[(size_t)Tn * Fn];
__device__ bf16 g_f1l[(size_t)Tn * Fn];
__device__ float g_f2[(size_t)Tn * Dn];

// ---------------- helpers ----------------------------------------------------
__device__ __forceinline__ uint32_t smem_u32(const void* p) {
    uint32_t a;
    asm("{ .reg .u64 t; cvta.to.shared.u64 t, %1; cvt.u32.u64 %0, t; }"
        : "=r"(a) : "l"(p));
    return a;
}
__device__ __forceinline__ void cp_async16(uint32_t s, const void* g) {
    asm volatile("cp.async.cg.shared.global [%0], [%1], 16;\n" :: "r"(s), "l"(g));
}
__device__ __forceinline__ void cp_commit() {
    asm volatile("cp.async.commit_group;\n" ::);
}
__device__ __forceinline__ void cp_wait0() {
    asm volatile("cp.async.wait_group 0;\n" ::);
}
__device__ __forceinline__ void cp_wait1() {
    asm volatile("cp.async.wait_group 1;\n" ::);
}
__device__ __forceinline__ void ldsm4(uint32_t* r, uint32_t addr) {
    asm volatile("ldmatrix.sync.aligned.m8n8.x4.shared.b16 {%0,%1,%2,%3}, [%4];"
                 : "=r"(r[0]), "=r"(r[1]), "=r"(r[2]), "=r"(r[3]) : "r"(addr));
}
__device__ __forceinline__ void mma16816(float* c, const uint32_t* a,
                                         uint32_t b0, uint32_t b1) {
    asm volatile(
        "mma.sync.aligned.m16n8k16.row.col.f32.bf16.bf16.f32 "
        "{%0,%1,%2,%3}, {%4,%5,%6,%7}, {%8,%9}, {%0,%1,%2,%3};"
        : "+f"(c[0]), "+f"(c[1]), "+f"(c[2]), "+f"(c[3])
        : "r"(a[0]), "r"(a[1]), "r"(a[2]), "r"(a[3]), "r"(b0), "r"(b1));
}
__device__ __forceinline__ void split2(float a, float b, bf162& h, bf162& l) {
    h = __floats2bfloat162_rn(a, b);
    float2 f = __bfloat1622float2(h);
    l = __floats2bfloat162_rn(a - f.x, b - f.y);
}

// ---------------- pipelined bf16-split HMMA GEMM -----------------------------
// C[m,n] = alpha*sum_k (Ah+Al)[m,k]*(Bh+Bl)[n,k] (3-term) (+bias) (opt relu).
// A,B bf16 row-major. M%128==0, N%TSN==0, K%32==0. 256 thr, warps 2m x 4n.
#define RSTR 80   // smem row stride bytes (64B data + 16B pad)

template <int TSN, bool OUTBF, bool BIAS, bool RELU>
__global__ __launch_bounds__(256) void pgemm(
    const bf16* __restrict__ Ah_, const bf16* __restrict__ Al_,
    const bf16* __restrict__ Bh_, const bf16* __restrict__ Bl_,
    const float* __restrict__ bias, float* __restrict__ Cf,
    bf16* __restrict__ Ch, bf16* __restrict__ Cl,
    int K, int lda, int ldb, int ldc,
    long long sAh, long long sAb, long long sBh, long long sBb,
    long long sCh, long long sCb, int bdiv, float alpha)
{
    constexpr int WN = TSN / 4;
    constexpr int NT = WN / 8;
    constexpr int ABYT = 128 * RSTR;
    constexpr int BBYT = TSN * RSTR;
    constexpr int STAGE = 2 * ABYT + 2 * BBYT;

    extern __shared__ char sm[];
    uint32_t sb = smem_u32(sm);

    int tid = threadIdx.x, lane = tid & 31, wid = tid >> 5;
    int wm = wid & 1, wn = wid >> 1;

    int z = blockIdx.z;
    int h = z / bdiv, b = z % bdiv;
    const bf16* Ahb = Ah_ + h * sAh + b * sAb;
    const bf16* Alb = Al_ + h * sAh + b * sAb;
    const bf16* Bhb = Bh_ + h * sBh + b * sBb;
    const bf16* Blb = Bl_ + h * sBh + b * sBb;

    long long m0 = (long long)blockIdx.y * 128;
    int n0 = blockIdx.x * TSN;

    // staging maps
    int arow = tid >> 1;
    uint32_t aoff = arow * RSTR + (tid & 1) * 32;
    const bf16* gAh = Ahb + (m0 + arow) * (long long)lda + (tid & 1) * 16;
    const bf16* gAl = Alb + (m0 + arow) * (long long)lda + (tid & 1) * 16;
    int brow;
    uint32_t boff;
    const bf16 *gBh, *gBl;
    if (TSN == 128) {
        brow = tid >> 1;
        boff = brow * RSTR + (tid & 1) * 32;
        gBh = Bhb + (long long)(n0 + brow) * ldb + (tid & 1) * 16;
        gBl = Blb + (long long)(n0 + brow) * ldb + (tid & 1) * 16;
    } else {
        brow = tid >> 2;
        boff = brow * RSTR + (tid & 3) * 16;
        gBh = Bhb + (long long)(n0 + brow) * ldb + (tid & 3) * 8;
        gBl = Blb + (long long)(n0 + brow) * ldb + (tid & 3) * 8;
    }

    int lrow = lane & 15, lhalf = lane >> 4;
    uint32_t pAo = (wm * 64 + lrow) * RSTR + lhalf * 16;
    uint32_t pBo = 2 * ABYT + (wn * WN + lrow) * RSTR + lhalf * 16;

    float acc[4][NT][4];
#pragma unroll
    for (int i = 0; i < 4; i++)
#pragma unroll
        for (int j = 0; j < NT; j++)
#pragma unroll
            for (int q = 0; q < 4; q++) acc[i][j][q] = 0.0f;

    int ktiles = K / 32;

    auto load_stage = [&](int ktl, uint32_t sd) {
        long long ko = (long long)ktl * 32;
        cp_async16(sd + aoff, gAh + ko);
        cp_async16(sd + aoff + 16, gAh + ko + 8);
        cp_async16(sd + ABYT + aoff, gAl + ko);
        cp_async16(sd + ABYT + aoff + 16, gAl + ko + 8);
        if (TSN == 128) {
            cp_async16(sd + 2 * ABYT + boff, gBh + ko);
            cp_async16(sd + 2 * ABYT + boff + 16, gBh + ko + 8);
            cp_async16(sd + 2 * ABYT + BBYT + boff, gBl + ko);
            cp_async16(sd + 2 * ABYT + BBYT + boff + 16, gBl + ko + 8);
        } else {
            cp_async16(sd + 2 * ABYT + boff, gBh + ko);
            cp_async16(sd + 2 * ABYT + BBYT + boff, gBl + ko);
        }
    };

    load_stage(0, sb);
    cp_commit();

    for (int kt = 0; kt < ktiles; kt++) {
        int buf = kt & 1;
        bool more = (kt + 1) < ktiles;
        if (more) { load_stage(kt + 1, sb + (buf ^ 1) * STAGE); cp_commit(); }
        if (more) cp_wait1(); else cp_wait0();
        __syncthreads();

        uint32_t pA = sb + buf * STAGE + pAo;
        uint32_t pB = sb + buf * STAGE + pBo;
#pragma unroll
        for (int ks = 0; ks < 2; ks++) {
            uint32_t ah[4][4];
#pragma unroll
            for (int mt = 0; mt < 4; mt++)
                ldsm4(ah[mt], pA + mt * 16 * RSTR + ks * 32);
            uint32_t bh[NT / 2][4];
#pragma unroll
            for (int np = 0; np < NT / 2; np++)
                ldsm4(bh[np], pB + np * 16 * RSTR + ks * 32);
#pragma unroll
            for (int mt = 0; mt < 4; mt++)
#pragma unroll
                for (int np = 0; np < NT / 2; np++) {
                    mma16816(acc[mt][2 * np], ah[mt], bh[np][0], bh[np][2]);
                    mma16816(acc[mt][2 * np + 1], ah[mt], bh[np][1], bh[np][3]);
                }
            uint32_t al[4][4];
#pragma unroll
            for (int mt = 0; mt < 4; mt++)
                ldsm4(al[mt], pA + ABYT + mt * 16 * RSTR + ks * 32);
#pragma unroll
            for (int mt = 0; mt < 4; mt++)
#pragma unroll
                for (int np = 0; np < NT / 2; np++) {
                    mma16816(acc[mt][2 * np], al[mt], bh[np][0], bh[np][2]);
                    mma16816(acc[mt][2 * np + 1], al[mt], bh[np][1], bh[np][3]);
                }
            uint32_t bl[NT / 2][4];
#pragma unroll
            for (int np = 0; np < NT / 2; np++)
                ldsm4(bl[np], pB + BBYT + np * 16 * RSTR + ks * 32);
#pragma unroll
            for (int mt = 0; mt < 4; mt++)
#pragma unroll
                for (int np = 0; np < NT / 2; np++) {
                    mma16816(acc[mt][2 * np], ah[mt], bl[np][0], bl[np][2]);
                    mma16816(acc[mt][2 * np + 1], ah[mt], bl[np][1], bl[np][3]);
                }
        }
        __syncthreads();
    }

    // epilogue
    int g = lane >> 2, c2 = (lane & 3) * 2;
    long long hoff = h * sCh + b * sCb;
#pragma unroll
    for (int mt = 0; mt < 4; mt++) {
        long long r0 = m0 + wm * 64 + mt * 16 + g;
#pragma unroll
        for (int nt = 0; nt < NT; nt++) {
            int col = n0 + wn * WN + nt * 8 + c2;
            float v0 = acc[mt][nt][0] * alpha, v1 = acc[mt][nt][1] * alpha;
            float v2 = acc[mt][nt][2] * alpha, v3 = acc[mt][nt][3] * alpha;
            if (BIAS) {
                float b0 = bias[col], b1 = bias[col + 1];
                v0 += b0; v1 += b1; v2 += b0; v3 += b1;
            }
            if (RELU) {
                v0 = fmaxf(v0, 0.f); v1 = fmaxf(v1, 0.f);
                v2 = fmaxf(v2, 0.f); v3 = fmaxf(v3, 0.f);
            }
            if (OUTBF) {
                bf162 hh, ll;
                split2(v0, v1, hh, ll);
                *(bf162*)(Ch + hoff + r0 * ldc + col) = hh;
                *(bf162*)(Cl + hoff + r0 * ldc + col) = ll;
                split2(v2, v3, hh, ll);
                *(bf162*)(Ch + hoff + (r0 + 8) * ldc + col) = hh;
                *(bf162*)(Cl + hoff + (r0 + 8) * ldc + col) = ll;
            } else {
                float2 o0 = {v0, v1}, o1 = {v2, v3};
                *(float2*)(Cf + hoff + r0 * ldc + col) = o0;
                *(float2*)(Cf + hoff + (r0 + 8) * ldc + col) = o1;
            }
        }
    }
}

// ---------------- elementwise convert: fp32 -> bf16 hi/lo --------------------
__global__ __launch_bounds__(256) void cvt_kernel(
    const float* __restrict__ in, bf16* __restrict__ h, bf16* __restrict__ l)
{
    long long i = (long long)blockIdx.x * 256 + threadIdx.x;
    float4 v = reinterpret_cast<const float4*>(in)[i];
    bf162 h0, l0, h1, l1;
    split2(v.x, v.y, h0, l0);
    split2(v.z, v.w, h1, l1);
    reinterpret_cast<bf162*>(h)[2 * i] = h0;
    reinterpret_cast<bf162*>(h)[2 * i + 1] = h1;
    reinterpret_cast<bf162*>(l)[2 * i] = l0;
    reinterpret_cast<bf162*>(l)[2 * i + 1] = l1;
}

// ---------------- transpose+convert [Z][R][C] -> bf16 hi/lo [Z][C][R] --------
__global__ __launch_bounds__(256) void tc_kernel(
    const float* __restrict__ in, bf16* __restrict__ oh, bf16* __restrict__ ol,
    int R, int C)
{
    __shared__ float t[32][33];
    const float* ib = in + (long long)blockIdx.z * R * C;
    long long ob = (long long)blockIdx.z * R * C;
    int c0 = blockIdx.x * 32, r0 = blockIdx.y * 32;
    int x = threadIdx.x, y = threadIdx.y;
#pragma unroll
    for (int i = 0; i < 32; i += 8)
        t[y + i][x] = ib[(long long)(r0 + y + i) * C + c0 + x];
    __syncthreads();
#pragma unroll
    for (int i = 0; i < 32; i += 8) {
        float v = t[x][y + i];
        bf16 hv = __float2bfloat16_rn(v);
        bf16 lv = __float2bfloat16_rn(v - __bfloat162float(hv));
        long long o = ob + (long long)(c0 + y + i) * R + r0 + x;
        oh[o] = hv;
        ol[o] = lv;
    }
}

// ---------------- softmax (row=1024) -> bf16 hi/lo ---------------------------
__global__ __launch_bounds__(256) void softmax_kernel(
    const float* __restrict__ S, bf16* __restrict__ Ph, bf16* __restrict__ Pl)
{
    long long row = blockIdx.x;
    const float4* p = reinterpret_cast<const float4*>(S + row * Sn);
    int tid = threadIdx.x;
    float4 v = p[tid];
    __shared__ float red[256];
    float m = fmaxf(fmaxf(v.x, v.y), fmaxf(v.z, v.w));
    red[tid] = m;
    __syncthreads();
    for (int s = 128; s; s >>= 1) {
        if (tid < s) red[tid] = fmaxf(red[tid], red[tid + s]);
        __syncthreads();
    }
    float rmax = red[0];
    __syncthreads();
    v.x = expf(v.x - rmax); v.y = expf(v.y - rmax);
    v.z = expf(v.z - rmax); v.w = expf(v.w - rmax);
    red[tid] = v.x + v.y + v.z + v.w;
    __syncthreads();
    for (int s = 128; s; s >>= 1) {
        if (tid < s) red[tid] += red[tid + s];
        __syncthreads();
    }
    float inv = 1.0f / red[0];
    v.x *= inv; v.y *= inv; v.z *= inv; v.w *= inv;
    bf162 h0, l0, h1, l1;
    split2(v.x, v.y, h0, l0);
    split2(v.z, v.w, h1, l1);
    bf162* ph = reinterpret_cast<bf162*>(Ph + row * Sn);
    bf162* pl = reinterpret_cast<bf162*>(Pl + row * Sn);
    ph[2 * tid] = h0; ph[2 * tid + 1] = h1;
    pl[2 * tid] = l0; pl[2 * tid + 1] = l1;
}

// ---------------- residual add + LayerNorm (row=512) -------------------------
template <bool EMIT>
__global__ __launch_bounds__(128) void add_ln_kernel(
    const float* __restrict__ X, const float* __restrict__ Y,
    const float* __restrict__ gamma, const float* __restrict__ beta,
    float* __restrict__ out, bf16* __restrict__ oh, bf16* __restrict__ ol)
{
    long long row = blockIdx.x;
    int tid = threadIdx.x;
    const float4* x4 = reinterpret_cast<const float4*>(X + row * Dn);
    const float4* y4 = reinterpret_cast<const float4*>(Y + row * Dn);
    float4 a = x4[tid], c = y4[tid];
    float v0 = a.x + c.x, v1 = a.y + c.y, v2 = a.z + c.z, v3 = a.w + c.w;
    __shared__ float rs[128], rq[128];
    rs[tid] = v0 + v1 + v2 + v3;
    rq[tid] = v0 * v0 + v1 * v1 + v2 * v2 + v3 * v3;
    __syncthreads();
    for (int s = 64; s; s >>= 1) {
        if (tid < s) { rs[tid] += rs[tid + s]; rq[tid] += rq[tid + s]; }
        __syncthreads();
    }
    float mean = rs[0] * (1.0f / Dn);
    float var = rq[0] * (1.0f / Dn) - mean * mean;
    float rstd = rsqrtf(var + 1e-3f);
    float4 g = reinterpret_cast<const float4*>(gamma)[tid];
    float4 bb = reinterpret_cast<const float4*>(beta)[tid];
    float4 o;
    o.x = g.x * (v0 - mean) * rstd + bb.x;
    o.y = g.y * (v1 - mean) * rstd + bb.y;
    o.z = g.z * (v2 - mean) * rstd + bb.z;
    o.w = g.w * (v3 - mean) * rstd + bb.w;
    reinterpret_cast<float4*>(out + row * Dn)[tid] = o;
    if (EMIT) {
        bf162 h0, l0, h1, l1;
        split2(o.x, o.y, h0, l0);
        split2(o.z, o.w, h1, l1);
        bf162* ph = reinterpret_cast<bf162*>(oh + row * Dn);
        bf162* pl = reinterpret_cast<bf162*>(ol + row * Dn);
        ph[2 * tid] = h0; ph[2 * tid + 1] = h1;
        pl[2 * tid] = l0; pl[2 * tid + 1] = l1;
    }
}

// ---------------- launch -----------------------------------------------------
extern "C" void kernel_launch(void* const* d_in, const int* in_sizes, int n_in,
                              void* d_out, int out_size)
{
    const float* x  = (const float*)d_in[0];
    const float* qw = (const float*)d_in[1];
    const float* kw = (const float*)d_in[2];
    const float* vw = (const float*)d_in[3];
    const float* lw = (const float*)d_in[4];
    const float* g1 = (const float*)d_in[5];
    const float* b1v= (const float*)d_in[6];
    const float* w1 = (const float*)d_in[7];
    const float* bb1= (const float*)d_in[8];
    const float* w2 = (const float*)d_in[9];
    const float* bb2= (const float*)d_in[10];
    const float* g2 = (const float*)d_in[11];
    const float* b2v= (const float*)d_in[12];
    float* out = (float*)d_out;

#define GA(p, s) cudaGetSymbolAddress((void**)&p, s)
    bf16 *xh, *xl, *qwTh, *qwTl, *kwTh, *kwTl, *vwTh, *vwTl, *lwTh, *lwTl;
    bf16 *w1Th, *w1Tl, *w2Th, *w2Tl, *Qh, *Ql, *Kh, *Kl, *VTh, *VTl;
    bf16 *Ph, *Pl, *Ach, *Acl, *hbh, *hbl, *f1h, *f1l;
    float *S, *mha, *hb, *f2;
    GA(xh, g_xh); GA(xl, g_xl);
    GA(qwTh, g_qwTh); GA(qwTl, g_qwTl);
    GA(kwTh, g_kwTh); GA(kwTl, g_kwTl);
    GA(vwTh, g_vwTh); GA(vwTl, g_vwTl);
    GA(lwTh, g_lwTh); GA(lwTl, g_lwTl);
    GA(w1Th, g_w1Th); GA(w1Tl, g_w1Tl);
    GA(w2Th, g_w2Th); GA(w2Tl, g_w2Tl);
    GA(Qh, g_Qh); GA(Ql, g_Ql); GA(Kh, g_Kh); GA(Kl, g_Kl);
    GA(VTh, g_VTh); GA(VTl, g_VTl);
    GA(Ph, g_Ph); GA(Pl, g_Pl);
    GA(Ach, g_Ach); GA(Acl, g_Acl);
    GA(hbh, g_hbh); GA(hbl, g_hbl);
    GA(f1h, g_f1h); GA(f1l, g_f1l);
    GA(S, g_S); GA(mha, g_mha); GA(hb, g_hb); GA(f2, g_f2);
#undef GA

    constexpr int SM128 = 2 * (2 * 128 * RSTR + 2 * 128 * RSTR); // 81920
    constexpr int SM64  = 2 * (2 * 128 * RSTR + 2 * 64 * RSTR);  // 61440
    cudaFuncSetAttribute(pgemm<64, true, false, false>,
                         cudaFuncAttributeMaxDynamicSharedMemorySize, SM64);
    cudaFuncSetAttribute(pgemm<128, true, false, false>,
                         cudaFuncAttributeMaxDynamicSharedMemorySize, SM128);
    cudaFuncSetAttribute(pgemm<128, false, false, false>,
                         cudaFuncAttributeMaxDynamicSharedMemorySize, SM128);
    cudaFuncSetAttribute(pgemm<128, true, true, true>,
                         cudaFuncAttributeMaxDynamicSharedMemorySize, SM128);
    cudaFuncSetAttribute(pgemm<128, false, true, false>,
                         cudaFuncAttributeMaxDynamicSharedMemorySize, SM128);

    float scale = 1.0f / sqrtf((float)Dn);
    dim3 tb(32, 8);

    // operand preparation
    cvt_kernel<<<(Tn * Dn) / 1024, 256>>>(x, xh, xl);
    tc_kernel<<<dim3(Un / 32, Dn / 32, Hn), tb>>>(qw, qwTh, qwTl, Dn, Un);
    tc_kernel<<<dim3(Un / 32, Dn / 32, Hn), tb>>>(kw, kwTh, kwTl, Dn, Un);
    tc_kernel<<<dim3(Dn / 32, Dn / 32, Hn), tb>>>(vw, vwTh, vwTl, Dn, Dn);
    tc_kernel<<<dim3(Dn / 32, (Hn * Dn) / 32, 1), tb>>>(lw, lwTh, lwTl, Hn * Dn, Dn);
    tc_kernel<<<dim3(Fn / 32, Dn / 32, 1), tb>>>(w1, w1Th, w1Tl, Dn, Fn);
    tc_kernel<<<dim3(Dn / 32, Fn / 32, 1), tb>>>(w2, w2Th, w2Tl, Fn, Dn);

    // Q,K: [8192,64] = x @ qw[h], out bf16
    pgemm<64, true, false, false><<<dim3(1, Tn / 128, Hn), 256, SM64>>>(
        xh, xl, qwTh, qwTl, nullptr, nullptr, Qh, Ql,
        Dn, Dn, Dn, Un, 0, 0, (long long)Un * Dn, 0,
        (long long)Tn * Un, 0, 1, 1.0f);
    pgemm<64, true, false, false><<<dim3(1, Tn / 128, Hn), 256, SM64>>>(
        xh, xl, kwTh, kwTl, nullptr, nullptr, Kh, Kl,
        Dn, Dn, Dn, Un, 0, 0, (long long)Un * Dn, 0,
        (long long)Tn * Un, 0, 1, 1.0f);

    // VT[h] = vwT[h] @ x^T : [512, 8192], out bf16
    pgemm<128, true, false, false><<<dim3(Tn / 128, Dn / 128, Hn), 256, SM128>>>(
        vwTh, vwTl, xh, xl, nullptr, nullptr, VTh, VTl,
        Dn, Dn, Dn, Tn, (long long)Dn * Dn, 0, 0, 0,
        (long long)Dn * Tn, 0, 1, 1.0f);

    // scores = scale * Q @ K^T : [1024,1024], K=64, out fp32
    pgemm<128, false, false, false><<<dim3(Sn / 128, Sn / 128, Hn * Bn), 256, SM128>>>(
        Qh, Ql, Kh, Kl, nullptr, S, nullptr, nullptr,
        Un, Un, Un, Sn,
        (long long)Tn * Un, (long long)Sn * Un,
        (long long)Tn * Un, (long long)Sn * Un,
        (long long)Bn * Sn * Sn, (long long)Sn * Sn, Bn, scale);

    softmax_kernel<<<Hn * Bn * Sn, 256>>>(S, Ph, Pl);

    // attn = P @ VT[h][:, b]^T -> concat Ac, out bf16
    pgemm<128, true, false, false><<<dim3(Dn / 128, Sn / 128, Hn * Bn), 256, SM128>>>(
        Ph, Pl, VTh, VTl, nullptr, nullptr, Ach, Acl,
        Sn, Sn, Tn, Hn * Dn,
        (long long)Bn * Sn * Sn, (long long)Sn * Sn,
        (long long)Dn * Tn, (long long)Sn,
        (long long)Dn, (long long)Sn * Hn * Dn, Bn, 1.0f);

    // mha = Ac @ lw : [8192,512], K=4096, out fp32
    pgemm<128, false, false, false><<<dim3(Dn / 128, Tn / 128, 1), 256, SM128>>>(
        Ach, Acl, lwTh, lwTl, nullptr, mha, nullptr, nullptr,
        Hn * Dn, Hn * Dn, Hn * Dn, Dn, 0, 0, 0, 0, 0, 0, 1, 1.0f);

    add_ln_kernel<true><<<Tn, 128>>>(x, mha, g1, b1v, hb, hbh, hbl);

    // f1 = relu(hb @ w1 + b1) : [8192,2048], out bf16
    pgemm<128, true, true, true><<<dim3(Fn / 128, Tn / 128, 1), 256, SM128>>>(
        hbh, hbl, w1Th, w1Tl, bb1, nullptr, f1h, f1l,
        Dn, Dn, Dn, Fn, 0, 0, 0, 0, 0, 0, 1, 1.0f);

    // f2 = f1 @ w2 + b2 : [8192,512], K=2048, out fp32
    pgemm<128, false, true, false><<<dim3(Dn / 128, Tn / 128, 1), 256, SM128>>>(
        f1h, f1l, w2Th, w2Tl, bb2, f2, nullptr, nullptr,
        Fn, Fn, Fn, Dn, 0, 0, 0, 0, 0, 0, 1, 1.0f);

    add_ln_kernel<false><<<Tn, 128>>>(hb, f2, g2, b2v, out, nullptr, nullptr);
}

// round 9
// speedup vs baseline: 2.4418x; 2.4418x over previous
#include <cuda_runtime.h>
#include <cuda_fp16.h>
#include <cstdint>
#include <math.h>

#define Tn 8192
#define Sn 1024
#define Bn 8
#define Hn 8
#define Un 64
#define Dn 512
#define Fn 2048

// ---------------- scratch ----------------------------------------------------
__device__ __half g_xh[(size_t)Tn * Dn];
__device__ __half g_qwT[(size_t)Hn * Un * Dn];
__device__ __half g_kwT[(size_t)Hn * Un * Dn];
__device__ __half g_vwT[(size_t)Hn * Dn * Dn];
__device__ __half g_lwT[(size_t)Dn * Hn * Dn];
__device__ __half g_w1T[(size_t)Fn * Dn];
__device__ __half g_w2T[(size_t)Dn * Fn];
__device__ __half g_Q[(size_t)Hn * Tn * Un];
__device__ __half g_K[(size_t)Hn * Tn * Un];
__device__ __half g_VT[(size_t)Hn * Dn * Tn];
__device__ float  g_S[(size_t)Hn * Bn * Sn * Sn];
__device__ __half g_P[(size_t)Hn * Bn * Sn * Sn];
__device__ __half g_Ac[(size_t)Tn * Hn * Dn];
__device__ float  g_mha[(size_t)Tn * Dn];
__device__ float  g_hb[(size_t)Tn * Dn];
__device__ __half g_hbh[(size_t)Tn * Dn];
__device__ __half g_f1[(size_t)Tn * Fn];
__device__ float  g_f2[(size_t)Tn * Dn];

// ---------------- helpers ----------------------------------------------------
__device__ __forceinline__ uint32_t smem_u32(const void* p) {
    uint32_t a;
    asm("{ .reg .u64 t; cvta.to.shared.u64 t, %1; cvt.u32.u64 %0, t; }"
        : "=r"(a) : "l"(p));
    return a;
}
__device__ __forceinline__ void cp_async16(uint32_t s, const void* g) {
    asm volatile("cp.async.cg.shared.global [%0], [%1], 16;\n" :: "r"(s), "l"(g));
}
__device__ __forceinline__ void cp_commit() {
    asm volatile("cp.async.commit_group;\n" ::);
}
__device__ __forceinline__ void cp_wait2() {
    asm volatile("cp.async.wait_group 2;\n" ::);
}
__device__ __forceinline__ void ldsm4(uint32_t* r, uint32_t addr) {
    asm volatile("ldmatrix.sync.aligned.m8n8.x4.shared.b16 {%0,%1,%2,%3}, [%4];"
                 : "=r"(r[0]), "=r"(r[1]), "=r"(r[2]), "=r"(r[3]) : "r"(addr));
}
__device__ __forceinline__ void mma16816(float* c, const uint32_t* a,
                                         uint32_t b0, uint32_t b1) {
    asm volatile(
        "mma.sync.aligned.m16n8k16.row.col.f32.f16.f16.f32 "
        "{%0,%1,%2,%3}, {%4,%5,%6,%7}, {%8,%9}, {%0,%1,%2,%3};"
        : "+f"(c[0]), "+f"(c[1]), "+f"(c[2]), "+f"(c[3])
        : "r"(a[0]), "r"(a[1]), "r"(a[2]), "r"(a[3]), "r"(b0), "r"(b1));
}

// ---------------- pipelined fp16 HMMA GEMM -----------------------------------
// C[m,n] = alpha * sum_k A[m,k]*B[n,k] (+bias[n]) (opt relu).
// A,B fp16 row-major. M%128==0, N%TSN==0, K%32==0. 256 thr, warps 2m x 4n.
// 4-stage cp.async ring, 2-deep prefetch, one __syncthreads per k-tile.
#define RSTR 80   // smem row stride bytes (64B data + 16B pad)

template <int TSN, bool OUTH, bool BIAS, bool RELU>
__global__ __launch_bounds__(256) void pgemm(
    const __half* __restrict__ A_, const __half* __restrict__ B_,
    const float* __restrict__ bias, float* __restrict__ Cf,
    __half* __restrict__ Ch,
    int K, int lda, int ldb, int ldc,
    long long sAh, long long sAb, long long sBh, long long sBb,
    long long sCh, long long sCb, int bdiv, float alpha)
{
    constexpr int WN = TSN / 4;
    constexpr int NT = WN / 8;
    constexpr int ABYT = 128 * RSTR;
    constexpr int BBYT = TSN * RSTR;
    constexpr int STAGE = ABYT + BBYT;

    extern __shared__ char sm[];
    uint32_t sb = smem_u32(sm);

    int tid = threadIdx.x, lane = tid & 31, wid = tid >> 5;
    int wm = wid & 1, wn = wid >> 1;

    int z = blockIdx.z;
    int h = z / bdiv, b = z % bdiv;
    const __half* Ab = A_ + h * sAh + b * sAb;
    const __half* Bb = B_ + h * sBh + b * sBb;

    long long m0 = (long long)blockIdx.y * 128;
    int n0 = blockIdx.x * TSN;

    // staging maps
    int arow = tid >> 1;
    uint32_t aoff = arow * RSTR + (tid & 1) * 32;
    const __half* gA = Ab + (m0 + arow) * (long long)lda + (tid & 1) * 16;
    uint32_t boff;
    const __half* gB;
    if (TSN == 128) {
        int brow = tid >> 1;
        boff = ABYT + brow * RSTR + (tid & 1) * 32;
        gB = Bb + (long long)(n0 + brow) * ldb + (tid & 1) * 16;
    } else {
        int brow = tid >> 2;
        boff = ABYT + brow * RSTR + (tid & 3) * 16;
        gB = Bb + (long long)(n0 + brow) * ldb + (tid & 3) * 8;
    }

    int lrow = lane & 15, lhalf = lane >> 4;
    uint32_t pAo = (wm * 64 + lrow) * RSTR + lhalf * 16;
    uint32_t pBo = ABYT + (wn * WN + lrow) * RSTR + lhalf * 16;

    float acc[4][NT][4];
#pragma unroll
    for (int i = 0; i < 4; i++)
#pragma unroll
        for (int j = 0; j < NT; j++)
#pragma unroll
            for (int q = 0; q < 4; q++) acc[i][j][q] = 0.0f;

    int ktiles = K / 32;

    auto load_stage = [&](int ktl, uint32_t sd) {
        long long ko = (long long)ktl * 32;
        cp_async16(sd + aoff, gA + ko);
        cp_async16(sd + aoff + 16, gA + ko + 8);
        if (TSN == 128) {
            cp_async16(sd + boff, gB + ko);
            cp_async16(sd + boff + 16, gB + ko + 8);
        } else {
            cp_async16(sd + boff, gB + ko);
        }
    };

    load_stage(0, sb);
    cp_commit();
    if (ktiles > 1) load_stage(1, sb + STAGE);
    cp_commit();

    for (int kt = 0; kt < ktiles; kt++) {
        int buf = kt & 3;
        if (kt + 2 < ktiles) load_stage(kt + 2, sb + ((kt + 2) & 3) * STAGE);
        cp_commit();            // group every iteration keeps wait-count uniform
        cp_wait2();             // groups kt+1, kt+2 may be pending; kt complete
        __syncthreads();

        uint32_t pA = sb + buf * STAGE + pAo;
        uint32_t pB = sb + buf * STAGE + pBo;
#pragma unroll
        for (int ks = 0; ks < 2; ks++) {
            uint32_t af[4][4];
#pragma unroll
            for (int mt = 0; mt < 4; mt++)
                ldsm4(af[mt], pA + mt * 16 * RSTR + ks * 32);
            uint32_t bf[NT / 2][4];
#pragma unroll
            for (int np = 0; np < NT / 2; np++)
                ldsm4(bf[np], pB + np * 16 * RSTR + ks * 32);
#pragma unroll
            for (int mt = 0; mt < 4; mt++)
#pragma unroll
                for (int np = 0; np < NT / 2; np++) {
                    mma16816(acc[mt][2 * np], af[mt], bf[np][0], bf[np][2]);
                    mma16816(acc[mt][2 * np + 1], af[mt], bf[np][1], bf[np][3]);
                }
        }
        // no trailing sync: buffer reused 4 iterations later (>= 2 syncs apart)
    }

    // epilogue
    int g = lane >> 2, c2 = (lane & 3) * 2;
    long long hoff = h * sCh + b * sCb;
#pragma unroll
    for (int mt = 0; mt < 4; mt++) {
        long long r0 = m0 + wm * 64 + mt * 16 + g;
#pragma unroll
        for (int nt = 0; nt < NT; nt++) {
            int col = n0 + wn * WN + nt * 8 + c2;
            float v0 = acc[mt][nt][0] * alpha, v1 = acc[mt][nt][1] * alpha;
            float v2 = acc[mt][nt][2] * alpha, v3 = acc[mt][nt][3] * alpha;
            if (BIAS) {
                float b0 = bias[col], b1 = bias[col + 1];
                v0 += b0; v1 += b1; v2 += b0; v3 += b1;
            }
            if (RELU) {
                v0 = fmaxf(v0, 0.f); v1 = fmaxf(v1, 0.f);
                v2 = fmaxf(v2, 0.f); v3 = fmaxf(v3, 0.f);
            }
            if (OUTH) {
                *(__half2*)(Ch + hoff + r0 * ldc + col) = __floats2half2_rn(v0, v1);
                *(__half2*)(Ch + hoff + (r0 + 8) * ldc + col) = __floats2half2_rn(v2, v3);
            } else {
                float2 o0 = {v0, v1}, o1 = {v2, v3};
                *(float2*)(Cf + hoff + r0 * ldc + col) = o0;
                *(float2*)(Cf + hoff + (r0 + 8) * ldc + col) = o1;
            }
        }
    }
}

// ---------------- elementwise convert: fp32 -> fp16 --------------------------
__global__ __launch_bounds__(256) void cvt_kernel(
    const float* __restrict__ in, __half* __restrict__ o)
{
    long long i = (long long)blockIdx.x * 256 + threadIdx.x;
    float4 v = reinterpret_cast<const float4*>(in)[i];
    reinterpret_cast<__half2*>(o)[2 * i] = __floats2half2_rn(v.x, v.y);
    reinterpret_cast<__half2*>(o)[2 * i + 1] = __floats2half2_rn(v.z, v.w);
}

// ---------------- transpose+convert [Z][R][C] -> fp16 [Z][C][R] --------------
__global__ __launch_bounds__(256) void tc_kernel(
    const float* __restrict__ in, __half* __restrict__ o, int R, int C)
{
    __shared__ float t[32][33];
    const float* ib = in + (long long)blockIdx.z * R * C;
    long long ob = (long long)blockIdx.z * R * C;
    int c0 = blockIdx.x * 32, r0 = blockIdx.y * 32;
    int x = threadIdx.x, y = threadIdx.y;
#pragma unroll
    for (int i = 0; i < 32; i += 8)
        t[y + i][x] = ib[(long long)(r0 + y + i) * C + c0 + x];
    __syncthreads();
#pragma unroll
    for (int i = 0; i < 32; i += 8)
        o[ob + (long long)(c0 + y + i) * R + r0 + x] = __float2half_rn(t[x][y + i]);
}

// ---------------- softmax (row=1024) -> fp16 --------------------------------
__global__ __launch_bounds__(256) void softmax_kernel(
    const float* __restrict__ S, __half* __restrict__ P)
{
    long long row = blockIdx.x;
    const float4* p = reinterpret_cast<const float4*>(S + row * Sn);
    int tid = threadIdx.x;
    float4 v = p[tid];
    __shared__ float red[256];
    float m = fmaxf(fmaxf(v.x, v.y), fmaxf(v.z, v.w));
    red[tid] = m;
    __syncthreads();
    for (int s = 128; s; s >>= 1) {
        if (tid < s) red[tid] = fmaxf(red[tid], red[tid + s]);
        __syncthreads();
    }
    float rmax = red[0];
    __syncthreads();
    v.x = expf(v.x - rmax); v.y = expf(v.y - rmax);
    v.z = expf(v.z - rmax); v.w = expf(v.w - rmax);
    red[tid] = v.x + v.y + v.z + v.w;
    __syncthreads();
    for (int s = 128; s; s >>= 1) {
        if (tid < s) red[tid] += red[tid + s];
        __syncthreads();
    }
    float inv = 1.0f / red[0];
    __half2* ph = reinterpret_cast<__half2*>(P + row * Sn);
    ph[2 * tid] = __floats2half2_rn(v.x * inv, v.y * inv);
    ph[2 * tid + 1] = __floats2half2_rn(v.z * inv, v.w * inv);
}

// ---------------- residual add + LayerNorm (row=512) -------------------------
template <bool EMIT>
__global__ __launch_bounds__(128) void add_ln_kernel(
    const float* __restrict__ X, const float* __restrict__ Y,
    const float* __restrict__ gamma, const float* __restrict__ beta,
    float* __restrict__ out, __half* __restrict__ oh)
{
    long long row = blockIdx.x;
    int tid = threadIdx.x;
    const float4* x4 = reinterpret_cast<const float4*>(X + row * Dn);
    const float4* y4 = reinterpret_cast<const float4*>(Y + row * Dn);
    float4 a = x4[tid], c = y4[tid];
    float v0 = a.x + c.x, v1 = a.y + c.y, v2 = a.z + c.z, v3 = a.w + c.w;
    __shared__ float rs[128], rq[128];
    rs[tid] = v0 + v1 + v2 + v3;
    rq[tid] = v0 * v0 + v1 * v1 + v2 * v2 + v3 * v3;
    __syncthreads();
    for (int s = 64; s; s >>= 1) {
        if (tid < s) { rs[tid] += rs[tid + s]; rq[tid] += rq[tid + s]; }
        __syncthreads();
    }
    float mean = rs[0] * (1.0f / Dn);
    float var = rq[0] * (1.0f / Dn) - mean * mean;
    float rstd = rsqrtf(var + 1e-3f);
    float4 g = reinterpret_cast<const float4*>(gamma)[tid];
    float4 bb = reinterpret_cast<const float4*>(beta)[tid];
    float4 o;
    o.x = g.x * (v0 - mean) * rstd + bb.x;
    o.y = g.y * (v1 - mean) * rstd + bb.y;
    o.z = g.z * (v2 - mean) * rstd + bb.z;
    o.w = g.w * (v3 - mean) * rstd + bb.w;
    reinterpret_cast<float4*>(out + row * Dn)[tid] = o;
    if (EMIT) {
        __half2* ph = reinterpret_cast<__half2*>(oh + row * Dn);
        ph[2 * tid] = __floats2half2_rn(o.x, o.y);
        ph[2 * tid + 1] = __floats2half2_rn(o.z, o.w);
    }
}

// ---------------- launch -----------------------------------------------------
extern "C" void kernel_launch(void* const* d_in, const int* in_sizes, int n_in,
                              void* d_out, int out_size)
{
    const float* x  = (const float*)d_in[0];
    const float* qw = (const float*)d_in[1];
    const float* kw = (const float*)d_in[2];
    const float* vw = (const float*)d_in[3];
    const float* lw = (const float*)d_in[4];
    const float* g1 = (const float*)d_in[5];
    const float* b1v= (const float*)d_in[6];
    const float* w1 = (const float*)d_in[7];
    const float* bb1= (const float*)d_in[8];
    const float* w2 = (const float*)d_in[9];
    const float* bb2= (const float*)d_in[10];
    const float* g2 = (const float*)d_in[11];
    const float* b2v= (const float*)d_in[12];
    float* out = (float*)d_out;

#define GA(p, s) cudaGetSymbolAddress((void**)&p, s)
    __half *xh, *qwT, *kwT, *vwT, *lwT, *w1T, *w2T;
    __half *Q, *K, *VT, *P, *Ac, *hbh, *f1;
    float *S, *mha, *hb, *f2;
    GA(xh, g_xh);
    GA(qwT, g_qwT); GA(kwT, g_kwT); GA(vwT, g_vwT); GA(lwT, g_lwT);
    GA(w1T, g_w1T); GA(w2T, g_w2T);
    GA(Q, g_Q); GA(K, g_K); GA(VT, g_VT);
    GA(P, g_P); GA(Ac, g_Ac); GA(hbh, g_hbh); GA(f1, g_f1);
    GA(S, g_S); GA(mha, g_mha); GA(hb, g_hb); GA(f2, g_f2);
#undef GA

    constexpr int SM128 = 4 * (128 * RSTR + 128 * RSTR); // 81920
    constexpr int SM64  = 4 * (128 * RSTR + 64 * RSTR);  // 61440
    cudaFuncSetAttribute(pgemm<64, true, false, false>,
                         cudaFuncAttributeMaxDynamicSharedMemorySize, SM64);
    cudaFuncSetAttribute(pgemm<128, true, false, false>,
                         cudaFuncAttributeMaxDynamicSharedMemorySize, SM128);
    cudaFuncSetAttribute(pgemm<128, false, false, false>,
                         cudaFuncAttributeMaxDynamicSharedMemorySize, SM128);
    cudaFuncSetAttribute(pgemm<128, true, true, true>,
                         cudaFuncAttributeMaxDynamicSharedMemorySize, SM128);
    cudaFuncSetAttribute(pgemm<128, false, true, false>,
                         cudaFuncAttributeMaxDynamicSharedMemorySize, SM128);

    float scale = 1.0f / sqrtf((float)Dn);
    dim3 tb(32, 8);

    // operand preparation (fp16, weights transposed)
    cvt_kernel<<<(Tn * Dn) / 1024, 256>>>(x, xh);
    tc_kernel<<<dim3(Un / 32, Dn / 32, Hn), tb>>>(qw, qwT, Dn, Un);
    tc_kernel<<<dim3(Un / 32, Dn / 32, Hn), tb>>>(kw, kwT, Dn, Un);
    tc_kernel<<<dim3(Dn / 32, Dn / 32, Hn), tb>>>(vw, vwT, Dn, Dn);
    tc_kernel<<<dim3(Dn / 32, (Hn * Dn) / 32, 1), tb>>>(lw, lwT, Hn * Dn, Dn);
    tc_kernel<<<dim3(Fn / 32, Dn / 32, 1), tb>>>(w1, w1T, Dn, Fn);
    tc_kernel<<<dim3(Dn / 32, Fn / 32, 1), tb>>>(w2, w2T, Fn, Dn);

    // Q,K: [8192,64] = x @ qw[h]
    pgemm<64, true, false, false><<<dim3(1, Tn / 128, Hn), 256, SM64>>>(
        xh, qwT, nullptr, nullptr, Q,
        Dn, Dn, Dn, Un, 0, 0, (long long)Un * Dn, 0,
        (long long)Tn * Un, 0, 1, 1.0f);
    pgemm<64, true, false, false><<<dim3(1, Tn / 128, Hn), 256, SM64>>>(
        xh, kwT, nullptr, nullptr, K,
        Dn, Dn, Dn, Un, 0, 0, (long long)Un * Dn, 0,
        (long long)Tn * Un, 0, 1, 1.0f);

    // VT[h] = vwT[h] @ x^T : [512, 8192]
    pgemm<128, true, false, false><<<dim3(Tn / 128, Dn / 128, Hn), 256, SM128>>>(
        vwT, xh, nullptr, nullptr, VT,
        Dn, Dn, Dn, Tn, (long long)Dn * Dn, 0, 0, 0,
        (long long)Dn * Tn, 0, 1, 1.0f);

    // scores = scale * Q @ K^T : [1024,1024], K=64, out fp32
    pgemm<128, false, false, false><<<dim3(Sn / 128, Sn / 128, Hn * Bn), 256, SM128>>>(
        Q, K, nullptr, S, nullptr,
        Un, Un, Un, Sn,
        (long long)Tn * Un, (long long)Sn * Un,
        (long long)Tn * Un, (long long)Sn * Un,
        (long long)Bn * Sn * Sn, (long long)Sn * Sn, Bn, scale);

    softmax_kernel<<<Hn * Bn * Sn, 256>>>(S, P);

    // attn = P @ VT[h][:, b]^T -> concat Ac
    pgemm<128, true, false, false><<<dim3(Dn / 128, Sn / 128, Hn * Bn), 256, SM128>>>(
        P, VT, nullptr, nullptr, Ac,
        Sn, Sn, Tn, Hn * Dn,
        (long long)Bn * Sn * Sn, (long long)Sn * Sn,
        (long long)Dn * Tn, (long long)Sn,
        (long long)Dn, (long long)Sn * Hn * Dn, Bn, 1.0f);

    // mha = Ac @ lw : [8192,512], K=4096, out fp32
    pgemm<128, false, false, false><<<dim3(Dn / 128, Tn / 128, 1), 256, SM128>>>(
        Ac, lwT, nullptr, mha, nullptr,
        Hn * Dn, Hn * Dn, Hn * Dn, Dn, 0, 0, 0, 0, 0, 0, 1, 1.0f);

    add_ln_kernel<true><<<Tn, 128>>>(x, mha, g1, b1v, hb, hbh);

    // f1 = relu(hb @ w1 + b1) : [8192,2048]
    pgemm<128, true, true, true><<<dim3(Fn / 128, Tn / 128, 1), 256, SM128>>>(
        hbh, w1T, bb1, nullptr, f1,
        Dn, Dn, Dn, Fn, 0, 0, 0, 0, 0, 0, 1, 1.0f);

    // f2 = f1 @ w2 + b2 : [8192,512], K=2048, out fp32
    pgemm<128, false, true, false><<<dim3(Dn / 128, Tn / 128, 1), 256, SM128>>>(
        f1, w2T, bb2, f2, nullptr,
        Fn, Fn, Fn, Dn, 0, 0, 0, 0, 0, 0, 1, 1.0f);

    add_ln_kernel<false><<<Tn, 128>>>(hb, f2, g2, b2v, out, nullptr);
}